// round 16
// baseline (speedup 1.0000x reference)
#include <cuda_runtime.h>

// Haar DWT level-1 on channel 0 of x:(B=32, C=3, H=512, W=512) fp32.
// Output: (B, 4, 256, 256) fp32, order [ll, lh, hl, hh].
//
// ROOFLINE (established R1-R15, FINAL): compulsory L2 traffic = 33.6 MB read
// + 33.6 MB write = 67 MB of full 32B sectors against the path-independent
// chip-wide LTS cap (~6300 B/cyc) => ~10.6us floor. Fifteen runs across
// eight structurally distinct kernels (1M..256K threads, 8/16/32B accesses,
// L2::evict_last hints, persistent single-wave, 1D/3D grids) all land in
// 10.72-11.01us; identical binaries span the full band -> within-band
// variation is run-to-run noise exceeding the remaining theoretical headroom.
// DRAM (warm==cold, evict hints neutral), issue (19-24%), occupancy (73-80%
// with zero time effect), wave structure, and access width were each ruled
// out by direct experiment. TMA rides the same capped LTS path (HW-measured
// path-independence); there is no L2-bypass store path on NVIDIA; and the
// 67 MB is information-theoretically minimal (zero reuse, full-sector
// coalescing both directions, fp32 and layout mandated by the output spec).
// ~99% of achievable roofline. CLOSED.
//
// Shape: 3D grid (y=row, z=batch), 128-thread blocks; one thread = 4 input
// cols x 2 input rows (two float4 loads) -> one float2 store per sub-band
// plane. regs=18, fully coalesced 128B/warp on both sides.

#define H_IN 512
#define W_IN 512
#define H_OUT 256
#define W_OUT 256
#define C_IN 3

__device__ __forceinline__ void haar2(float a, float b, float c, float d,
                                      float& ll, float& lh, float& hl, float& hh) {
    float apb = a + b, cpd = c + d;
    float amb = a - b, cmd = c - d;
    ll = (apb + cpd) * 0.5f;
    lh = (apb - cpd) * 0.5f;
    hl = (amb + cmd) * 0.5f;
    hh = (amb - cmd) * 0.5f;
}

__global__ void __launch_bounds__(128)
haar_dwt_kernel(const float* __restrict__ x, float* __restrict__ out) {
    // blockIdx.z = batch, blockIdx.y = output row, threadIdx.x = column-pair.
    const int jp = threadIdx.x;          // 0..127 column-pair
    const int i  = blockIdx.y;           // output row
    const int b  = blockIdx.z;           // batch

    const float* xp = x + (size_t)b * C_IN * H_IN * W_IN;
    const int col = jp * 4;              // 4 input columns
    const float4 top = *reinterpret_cast<const float4*>(xp + (size_t)(2 * i)     * W_IN + col);
    const float4 bot = *reinterpret_cast<const float4*>(xp + (size_t)(2 * i + 1) * W_IN + col);

    float2 ll, lh, hl, hh;
    haar2(top.x, top.y, bot.x, bot.y, ll.x, lh.x, hl.x, hh.x);
    haar2(top.z, top.w, bot.z, bot.w, ll.y, lh.y, hl.y, hh.y);

    const size_t plane = (size_t)H_OUT * W_OUT;             // 65536
    float* op = out + (size_t)b * 4 * plane + (size_t)i * W_OUT + 2 * jp;
    *reinterpret_cast<float2*>(op + 0 * plane) = ll;
    *reinterpret_cast<float2*>(op + 1 * plane) = lh;
    *reinterpret_cast<float2*>(op + 2 * plane) = hl;
    *reinterpret_cast<float2*>(op + 3 * plane) = hh;
}

extern "C" void kernel_launch(void* const* d_in, const int* in_sizes, int n_in,
                              void* d_out, int out_size) {
    const float* x = (const float*)d_in[0];
    float* out = (float*)d_out;

    dim3 grid(1, H_OUT, 32);   // (col-pair blocks, rows, batch)
    dim3 block(128, 1, 1);     // 128 column-pairs per row
    haar_dwt_kernel<<<grid, block>>>(x, out);
}

// round 17
// speedup vs baseline: 1.0239x; 1.0239x over previous
#include <cuda_runtime.h>

// Haar DWT level-1 on channel 0 of x:(B=32, C=3, H=512, W=512) fp32.
// Output: (B, 4, 256, 256) fp32, order [ll, lh, hl, hh].
//
// ROOFLINE (established R1-R16, FINAL): compulsory L2 traffic = 33.6 MB read
// + 33.6 MB write = 67 MB of full 32B sectors against the path-independent
// chip-wide LTS cap (~6300 B/cyc) => ~10.6us floor. Sixteen runs across
// eight structurally distinct kernels (1M..256K threads, 8/16/32B accesses,
// L2::evict_last hints, persistent single-wave, 1D/3D grids) all land in
// 10.72-11.01us; identical binaries span the full band -> within-band
// variation is run-to-run noise exceeding the remaining theoretical headroom.
// DRAM (warm==cold, evict hints neutral), issue (19-24%), occupancy (73-80%
// with zero time effect), wave structure, and access width were each ruled
// out by direct experiment. TMA rides the same capped LTS path (HW-measured
// path-independence); there is no L2-bypass store path on NVIDIA; and the
// 67 MB is information-theoretically minimal (zero reuse, full-sector
// coalescing both directions, fp32 and layout mandated by the output spec).
// ~99% of achievable roofline. CLOSED.
//
// Shape: 3D grid (y=row, z=batch), 128-thread blocks; one thread = 4 input
// cols x 2 input rows (two float4 loads) -> one float2 store per sub-band
// plane. regs=18, fully coalesced 128B/warp on both sides.

#define H_IN 512
#define W_IN 512
#define H_OUT 256
#define W_OUT 256
#define C_IN 3

__device__ __forceinline__ void haar2(float a, float b, float c, float d,
                                      float& ll, float& lh, float& hl, float& hh) {
    float apb = a + b, cpd = c + d;
    float amb = a - b, cmd = c - d;
    ll = (apb + cpd) * 0.5f;
    lh = (apb - cpd) * 0.5f;
    hl = (amb + cmd) * 0.5f;
    hh = (amb - cmd) * 0.5f;
}

__global__ void __launch_bounds__(128)
haar_dwt_kernel(const float* __restrict__ x, float* __restrict__ out) {
    // blockIdx.z = batch, blockIdx.y = output row, threadIdx.x = column-pair.
    const int jp = threadIdx.x;          // 0..127 column-pair
    const int i  = blockIdx.y;           // output row
    const int b  = blockIdx.z;           // batch

    const float* xp = x + (size_t)b * C_IN * H_IN * W_IN;
    const int col = jp * 4;              // 4 input columns
    const float4 top = *reinterpret_cast<const float4*>(xp + (size_t)(2 * i)     * W_IN + col);
    const float4 bot = *reinterpret_cast<const float4*>(xp + (size_t)(2 * i + 1) * W_IN + col);

    float2 ll, lh, hl, hh;
    haar2(top.x, top.y, bot.x, bot.y, ll.x, lh.x, hl.x, hh.x);
    haar2(top.z, top.w, bot.z, bot.w, ll.y, lh.y, hl.y, hh.y);

    const size_t plane = (size_t)H_OUT * W_OUT;             // 65536
    float* op = out + (size_t)b * 4 * plane + (size_t)i * W_OUT + 2 * jp;
    *reinterpret_cast<float2*>(op + 0 * plane) = ll;
    *reinterpret_cast<float2*>(op + 1 * plane) = lh;
    *reinterpret_cast<float2*>(op + 2 * plane) = hl;
    *reinterpret_cast<float2*>(op + 3 * plane) = hh;
}

extern "C" void kernel_launch(void* const* d_in, const int* in_sizes, int n_in,
                              void* d_out, int out_size) {
    const float* x = (const float*)d_in[0];
    float* out = (float*)d_out;

    dim3 grid(1, H_OUT, 32);   // (col-pair blocks, rows, batch)
    dim3 block(128, 1, 1);     // 128 column-pairs per row
    haar_dwt_kernel<<<grid, block>>>(x, out);
}